// round 10
// baseline (speedup 1.0000x reference)
#include <cuda_runtime.h>
#include <cstdint>

#define BB 8
#define DD 128
#define HH 256
#define WW 256
#define HWW 65536
#define TT 16
#define HCC 28
#define NPB 784
#define NN 6272
#define PP 29
#define QQ 12
#define COLSZ 6285

#define LABELS_OFF ((long long)NN * COLSZ)
#define MASK_OFF   (2LL * NN * COLSZ)
#define QLT_OFF    (2LL * NN * COLSZ + NN)

__device__ __forceinline__ float to_tf32(float x) {
    float r;
    asm("cvt.rna.tf32.f32 %0, %1;" : "=f"(r) : "f"(x));
    return r;
}

__device__ __forceinline__ void mma_tf32(float c[4], const uint32_t a[4], const uint32_t b[2]) {
    asm volatile(
        "mma.sync.aligned.m16n8k8.row.col.f32.tf32.tf32.f32 "
        "{%0,%1,%2,%3}, {%4,%5,%6,%7}, {%8,%9}, {%0,%1,%2,%3};"
        : "+f"(c[0]), "+f"(c[1]), "+f"(c[2]), "+f"(c[3])
        : "r"(a[0]), "r"(a[1]), "r"(a[2]), "r"(a[3]), "r"(b[0]), "r"(b[1]));
}

__device__ __forceinline__ uint32_t smem_u32(const void* p) {
    uint32_t a;
    asm("{ .reg .u64 t; cvta.to.shared.u64 t, %1; cvt.u32.u64 %0, t; }" : "=r"(a) : "l"(p));
    return a;
}
__device__ __forceinline__ void cp16(uint32_t dst, const float* src) {
    asm volatile("cp.async.cg.shared.global [%0], [%1], 16;"
                 :: "r"(dst), "l"(__cvta_generic_to_global(src)) : "memory");
}
#define CP_COMMIT() asm volatile("cp.async.commit_group;" ::: "memory")
#define CP_WAIT(n)  asm volatile("cp.async.wait_group %0;" :: "n"(n) : "memory")

// ===================== problem constants =====================
__constant__ int2 c_pos[PP] = {
    {-3,0},
    {-2,-2},{-2,-1},{-2,0},{-2,1},{-2,2},
    {-1,-2},{-1,-1},{-1,0},{-1,1},{-1,2},
    {0,-3},{0,-2},{0,-1},{0,0},{0,1},{0,2},{0,3},
    {1,-2},{1,-1},{1,0},{1,1},{1,2},
    {2,-2},{2,-1},{2,0},{2,1},{2,2},
    {3,0}
};
__constant__ int2 c_neg[QQ] = {
    {-8,0},{-6,-4},{-6,4},{-4,-6},{-4,6},
    {0,-8},{0,8},
    {4,-6},{4,6},{6,-4},{6,4},{8,0}
};

__device__ int g_y1[NN], g_x1[NN];
__device__ int g_yd[NN], g_xd[NN];
__device__ int g_x2[NN], g_y2[NN];
__device__ __align__(16) float g_A[NN * DD];     // s_des1 row-major [n][k], tf32-rounded
__device__ __align__(16) float g_B[NN * DD];     // distr   row-major [q][k], tf32-rounded
__device__ __align__(16) float g_des2t[(long long)BB * HWW * DD];  // des2 NHWC

// ---------------------------------------------------------------------------
// Cell argmax sampling (first-max). Reference swaps x/y on unpack.
// ---------------------------------------------------------------------------
__global__ void sample_kernel(const float* __restrict__ det1,
                              const float* __restrict__ det2) {
    int t = blockIdx.x * blockDim.x + threadIdx.x;
    if (t >= 2 * NN) return;
    const float* det = (t < NN) ? det1 : det2;
    int s = (t < NN) ? t : (t - NN);
    int b = s / NPB;
    int r = s - b * NPB;
    int cy = r / HCC;
    int cx = r - cy * HCC;
    const float* base = det + (long long)b * HWW + (TT + cy * 8) * WW + (TT + cx * 8);
    float best = -__int_as_float(0x7f800000);
    int bi = 0, bj = 0;
    #pragma unroll
    for (int ii = 0; ii < 8; ii++) {
        #pragma unroll
        for (int jj = 0; jj < 8; jj++) {
            float v = base[ii * WW + jj];
            if (v > best) { best = v; bi = ii; bj = jj; }
        }
    }
    int y = TT + cx * 8 + bj;   // reference swap
    int x = TT + cy * 8 + bi;
    if (t < NN) { g_y1[s] = y; g_x1[s] = x; }
    else        { g_yd[s] = y; g_xd[s] = x; }
}

// ---------------------------------------------------------------------------
// Transpose des2 (B,C,H,W) -> NHWC. __ldcs: single-use streaming reads.
// ---------------------------------------------------------------------------
__global__ void __launch_bounds__(256) transpose_kernel(const float* __restrict__ des2) {
    __shared__ float t[128][33];
    int b = blockIdx.y;
    int p0 = blockIdx.x * 32;
    int w = threadIdx.x >> 5, l = threadIdx.x & 31;
    const float* src = des2 + (long long)b * DD * HWW + p0;
    #pragma unroll
    for (int i = 0; i < 16; i++) {
        int cch = w + 8 * i;
        t[cch][l] = __ldcs(&src[(long long)cch * HWW + l]);
    }
    __syncthreads();
    float* dst = g_des2t + ((long long)b * HWW + p0) * DD;
    #pragma unroll
    for (int j = 0; j < 4; j++) {
        int p = w + 8 * j;
        #pragma unroll
        for (int u = 0; u < 4; u++) {
            dst[p * DD + u * 32 + l] = t[u * 32 + l][p];
        }
    }
}

// ---------------------------------------------------------------------------
// Per-sample: s_des1 gather, distractor gather (fused), xy2+mask,
// pos(argmax)/neg scores, qlt, labels col 0. 4-way ILP over offsets.
// ---------------------------------------------------------------------------
__global__ void score_kernel(const float* __restrict__ des1,
                             const float* __restrict__ qlt1,
                             const float* __restrict__ qlt2,
                             const float* __restrict__ aflow,
                             float* __restrict__ out) {
    int s = blockIdx.x;
    int c = threadIdx.x;
    int b = s / NPB;
    __shared__ float sdes[128];
    __shared__ float spall[32];
    __shared__ int sxy[2];

    int y1 = g_y1[s], x1 = g_x1[s];
    float v = des1[((b * DD + c) * HH + y1) * WW + x1];
    sdes[c] = v;
    g_A[s * DD + c] = to_tf32(v);

    // fused distractor gather
    {
        long long pixd = (long long)b * HWW + g_yd[s] * WW + g_xd[s];
        g_B[s * DD + c] = to_tf32(g_des2t[pixd * DD + c]);
    }

    if (c == 0) {
        float ax = aflow[((b * 2 + 0) * HH + y1) * WW + x1];
        float ay = aflow[((b * 2 + 1) * HH + y1) * WW + x1];
        int xi = (int)(ax + 0.5f);
        int yi = (int)(ay + 0.5f);
        sxy[0] = xi; sxy[1] = yi;
        g_x2[s] = xi; g_y2[s] = yi;
        out[MASK_OFF + s] = (xi >= 0 && yi >= 0 && xi < WW && yi < HH) ? 1.0f : 0.0f;
        out[LABELS_OFF + (long long)s * COLSZ] = 1.0f;   // rest zeroed by memset
    }
    __syncthreads();

    int x2 = sxy[0], y2 = sxy[1];
    int w = c >> 5, l = c & 31;
    float4 a = *(const float4*)&sdes[l * 4];
    const float* dt = g_des2t + (long long)b * HWW * DD;

    // pos offsets: warp w handles p = w + 4u; 4-way ILP batches
    for (int base = w; base < PP; base += 16) {
        int pi[4];
        float sum[4];
        float4 dv[4];
        #pragma unroll
        for (int u = 0; u < 4; u++) {
            int p = base + 4 * u;
            pi[u] = (p < PP) ? p : base;
        }
        #pragma unroll
        for (int u = 0; u < 4; u++) {
            int xx = min(max(x2 + c_pos[pi[u]].x, 0), WW - 1);
            int yy = min(max(y2 + c_pos[pi[u]].y, 0), HH - 1);
            dv[u] = *(const float4*)(dt + (yy * WW + xx) * DD + l * 4);
        }
        #pragma unroll
        for (int u = 0; u < 4; u++)
            sum[u] = a.x * dv[u].x + a.y * dv[u].y + a.z * dv[u].z + a.w * dv[u].w;
        #pragma unroll
        for (int o = 16; o > 0; o >>= 1) {
            #pragma unroll
            for (int u = 0; u < 4; u++)
                sum[u] += __shfl_down_sync(0xffffffffu, sum[u], o);
        }
        if (l == 0) {
            #pragma unroll
            for (int u = 0; u < 4; u++) {
                int p = base + 4 * u;
                if (p < PP) spall[p] = sum[u];
            }
        }
    }
    // neg offsets
    {
        int qi[4];
        float sum[4];
        float4 dv[4];
        #pragma unroll
        for (int u = 0; u < 4; u++) {
            int q = w + 4 * u;
            qi[u] = (q < QQ) ? q : w;
        }
        #pragma unroll
        for (int u = 0; u < 4; u++) {
            int xx = min(max(x2 + c_neg[qi[u]].x, 0), WW - 1);
            int yy = min(max(y2 + c_neg[qi[u]].y, 0), HH - 1);
            dv[u] = *(const float4*)(dt + (yy * WW + xx) * DD + l * 4);
        }
        #pragma unroll
        for (int u = 0; u < 4; u++)
            sum[u] = a.x * dv[u].x + a.y * dv[u].y + a.z * dv[u].z + a.w * dv[u].w;
        #pragma unroll
        for (int o = 16; o > 0; o >>= 1) {
            #pragma unroll
            for (int u = 0; u < 4; u++)
                sum[u] += __shfl_down_sync(0xffffffffu, sum[u], o);
        }
        if (l == 0) {
            #pragma unroll
            for (int u = 0; u < 4; u++) {
                int q = w + 4 * u;
                if (q < QQ) out[(long long)s * COLSZ + 1 + q] = sum[u];
            }
        }
    }
    __syncthreads();

    if (c == 0) {
        float best = spall[0]; int bp = 0;
        #pragma unroll
        for (int p = 1; p < PP; p++) {
            if (spall[p] > best) { best = spall[p]; bp = p; }
        }
        out[(long long)s * COLSZ] = best;
        int selx = min(max(x2 + c_pos[bp].x, 0), WW - 1);
        int sely = min(max(y2 + c_pos[bp].y, 0), HH - 1);
        float q1 = qlt1[(long long)b * HWW + y1 * WW + x1];
        float q2 = qlt2[(long long)b * HWW + sely * WW + selx];
        out[QLT_OFF + s] = 0.5f * (q1 + q2);
    }
}

// ---------------------------------------------------------------------------
// dscores GEMM via mma.sync tf32 (m16n8k8). CTA tile 128x128, 512 threads,
// 16 warps in 4x4 grid, warp tile 32x32 (2x4 mma tiles, 32-float acc).
// 3-stage cp.async pipeline, 2 CTAs/SM (64 regs/thread) -> 50% occupancy.
// Grid exactly 49x49. Epilogue: dis2 mask + streaming stores.
// ---------------------------------------------------------------------------
#define GSTAGE_B 36864
#define GSMEM_B  (3 * GSTAGE_B)   // 110592 B

__global__ void __launch_bounds__(512, 2) gemm_kernel(float* __restrict__ out) {
    extern __shared__ char sm[];
    __shared__ int sqx[128], sqy[128], sqb[128];

    int tid = threadIdx.x;
    int wid = tid >> 5, lane = tid & 31;
    int gid = lane >> 2, t4 = lane & 3;
    int wm = wid >> 2, wn = wid & 3;   // 4x4 warp grid, warp tile 32x32
    int m0 = blockIdx.y * 128, n0 = blockIdx.x * 128;

    if (tid < 128) {
        int q = n0 + tid;
        sqx[tid] = g_xd[q]; sqy[tid] = g_yd[q]; sqb[tid] = q / NPB;
    }

    uint32_t sb = smem_u32(sm);
    int ldrow = tid >> 3, ldc4 = tid & 7;   // 64 rows per pass, 4 passes = 256 rows (A then B)

    auto issue = [&](int st, int kc) {
        uint32_t so = sb + st * GSTAGE_B;
        #pragma unroll
        for (int p = 0; p < 4; p++) {
            int row = ldrow + 64 * p;
            const float* src = (p < 2)
                ? &g_A[(m0 + row) * DD + kc * 32 + ldc4 * 4]
                : &g_B[(n0 + row - 128) * DD + kc * 32 + ldc4 * 4];
            cp16(so + row * 144 + ldc4 * 16, src);
        }
        CP_COMMIT();
    };

    issue(0, 0);
    issue(1, 1);

    float acc[2][4][4];
    #pragma unroll
    for (int i = 0; i < 2; i++)
        #pragma unroll
        for (int j = 0; j < 4; j++)
            #pragma unroll
            for (int cc = 0; cc < 4; cc++) acc[i][j][cc] = 0.0f;

    #pragma unroll
    for (int kc = 0; kc < 4; kc++) {
        if (kc < 3) { CP_WAIT(1); } else { CP_WAIT(0); }
        __syncthreads();

        if (kc + 2 < 4) issue((kc + 2) % 3, kc + 2);

        const float* As = (const float*)(sm + (kc % 3) * GSTAGE_B);
        const float* Bsp = As + 4608;

        #pragma unroll
        for (int kk = 0; kk < 4; kk++) {
            int kb = kk * 8;
            uint32_t af[2][4], bf[4][2];
            #pragma unroll
            for (int i = 0; i < 2; i++) {
                int r = wm * 32 + i * 16 + gid;
                af[i][0] = __float_as_uint(As[r * 36 + kb + t4]);
                af[i][1] = __float_as_uint(As[(r + 8) * 36 + kb + t4]);
                af[i][2] = __float_as_uint(As[r * 36 + kb + t4 + 4]);
                af[i][3] = __float_as_uint(As[(r + 8) * 36 + kb + t4 + 4]);
            }
            #pragma unroll
            for (int j = 0; j < 4; j++) {
                int nr = wn * 32 + j * 8 + gid;
                bf[j][0] = __float_as_uint(Bsp[nr * 36 + kb + t4]);
                bf[j][1] = __float_as_uint(Bsp[nr * 36 + kb + t4 + 4]);
            }
            #pragma unroll
            for (int i = 0; i < 2; i++)
                #pragma unroll
                for (int j = 0; j < 4; j++)
                    mma_tf32(acc[i][j], af[i], bf[j]);
        }
    }

    // Epilogue: scores with dis2 mask (streaming stores). Labels pre-zeroed.
    #pragma unroll
    for (int i = 0; i < 2; i++) {
        int r0 = m0 + wm * 32 + i * 16 + gid;
        int r1 = r0 + 8;
        int rx0 = g_x2[r0], ry0 = g_y2[r0], rb0 = r0 / NPB;
        int rx1 = g_x2[r1], ry1 = g_y2[r1], rb1 = r1 / NPB;
        long long s0 = (long long)r0 * COLSZ + 13 + n0;
        long long s1 = (long long)r1 * COLSZ + 13 + n0;
        #pragma unroll
        for (int j = 0; j < 4; j++) {
            int c0 = wn * 32 + j * 8 + t4 * 2;
            int c1 = c0 + 1;
            int dx, dy, d2;
            dx = sqx[c0] - rx0; dy = sqy[c0] - ry0;
            d2 = dx * dx + dy * dy + ((sqb[c0] != rb0) ? 9 : 0);
            __stcs(&out[s0 + c0], (d2 < 9) ? 0.0f : acc[i][j][0]);
            dx = sqx[c1] - rx0; dy = sqy[c1] - ry0;
            d2 = dx * dx + dy * dy + ((sqb[c1] != rb0) ? 9 : 0);
            __stcs(&out[s0 + c1], (d2 < 9) ? 0.0f : acc[i][j][1]);
            dx = sqx[c0] - rx1; dy = sqy[c0] - ry1;
            d2 = dx * dx + dy * dy + ((sqb[c0] != rb1) ? 9 : 0);
            __stcs(&out[s1 + c0], (d2 < 9) ? 0.0f : acc[i][j][2]);
            dx = sqx[c1] - rx1; dy = sqy[c1] - ry1;
            d2 = dx * dx + dy * dy + ((sqb[c1] != rb1) ? 9 : 0);
            __stcs(&out[s1 + c1], (d2 < 9) ? 0.0f : acc[i][j][3]);
        }
    }
}

extern "C" void kernel_launch(void* const* d_in, const int* in_sizes, int n_in,
                              void* d_out, int out_size) {
    const float* des1  = (const float*)d_in[0];
    const float* det1  = (const float*)d_in[1];
    const float* qlt1  = (const float*)d_in[2];
    const float* des2  = (const float*)d_in[3];
    const float* det2  = (const float*)d_in[4];
    const float* qlt2  = (const float*)d_in[5];
    const float* aflow = (const float*)d_in[6];
    float* out = (float*)d_out;

    cudaFuncSetAttribute(gemm_kernel, cudaFuncAttributeMaxDynamicSharedMemorySize, GSMEM_B);

    // Zero the labels plane up front (graph memset node); score sets col 0 = 1.
    cudaMemsetAsync(out + LABELS_OFF, 0, (size_t)NN * COLSZ * sizeof(float));

    sample_kernel<<<(2 * NN + 255) / 256, 256>>>(det1, det2);
    transpose_kernel<<<dim3(HWW / 32, BB), 256>>>(des2);
    score_kernel<<<NN, 128>>>(des1, qlt1, qlt2, aflow, out);
    gemm_kernel<<<dim3(49, 49), 512, GSMEM_B>>>(out);
}

// round 11
// speedup vs baseline: 1.0635x; 1.0635x over previous
#include <cuda_runtime.h>
#include <cstdint>

#define BB 8
#define DD 128
#define HH 256
#define WW 256
#define HWW 65536
#define TT 16
#define HCC 28
#define NPB 784
#define NN 6272
#define PP 29
#define QQ 12
#define COLSZ 6285

#define LABELS_OFF ((long long)NN * COLSZ)
#define MASK_OFF   (2LL * NN * COLSZ)
#define QLT_OFF    (2LL * NN * COLSZ + NN)

__device__ __forceinline__ float to_tf32(float x) {
    float r;
    asm("cvt.rna.tf32.f32 %0, %1;" : "=f"(r) : "f"(x));
    return r;
}

// k-permutation within each 8-group: order [k0,k4,k1,k5,k2,k6,k3,k7]
// so a fragment thread's (k=t4, k=t4+4) pair is contiguous -> LDS.64
__device__ __forceinline__ int kperm(int c) {
    return (c & ~7) | ((c & 3) << 1) | ((c & 4) >> 2);
}

__device__ __forceinline__ void mma_tf32(float c[4], const uint32_t a[4], const uint32_t b[2]) {
    asm volatile(
        "mma.sync.aligned.m16n8k8.row.col.f32.tf32.tf32.f32 "
        "{%0,%1,%2,%3}, {%4,%5,%6,%7}, {%8,%9}, {%0,%1,%2,%3};"
        : "+f"(c[0]), "+f"(c[1]), "+f"(c[2]), "+f"(c[3])
        : "r"(a[0]), "r"(a[1]), "r"(a[2]), "r"(a[3]), "r"(b[0]), "r"(b[1]));
}

__device__ __forceinline__ uint32_t smem_u32(const void* p) {
    uint32_t a;
    asm("{ .reg .u64 t; cvta.to.shared.u64 t, %1; cvt.u32.u64 %0, t; }" : "=r"(a) : "l"(p));
    return a;
}
__device__ __forceinline__ void cp16(uint32_t dst, const float* src) {
    asm volatile("cp.async.cg.shared.global [%0], [%1], 16;"
                 :: "r"(dst), "l"(__cvta_generic_to_global(src)) : "memory");
}
#define CP_COMMIT() asm volatile("cp.async.commit_group;" ::: "memory")
#define CP_WAIT(n)  asm volatile("cp.async.wait_group %0;" :: "n"(n) : "memory")

// ===================== problem constants =====================
__constant__ int2 c_pos[PP] = {
    {-3,0},
    {-2,-2},{-2,-1},{-2,0},{-2,1},{-2,2},
    {-1,-2},{-1,-1},{-1,0},{-1,1},{-1,2},
    {0,-3},{0,-2},{0,-1},{0,0},{0,1},{0,2},{0,3},
    {1,-2},{1,-1},{1,0},{1,1},{1,2},
    {2,-2},{2,-1},{2,0},{2,1},{2,2},
    {3,0}
};
__constant__ int2 c_neg[QQ] = {
    {-8,0},{-6,-4},{-6,4},{-4,-6},{-4,6},
    {0,-8},{0,8},
    {4,-6},{4,6},{6,-4},{6,4},{8,0}
};

__device__ int g_y1[NN], g_x1[NN];
__device__ int g_yd[NN], g_xd[NN];
__device__ int g_x2[NN], g_y2[NN];
__device__ __align__(16) float g_A[NN * DD];     // s_des1 [n][kperm], tf32-rounded
__device__ __align__(16) float g_B[NN * DD];     // distr  [q][kperm], tf32-rounded
__device__ __align__(16) float g_des2t[(long long)BB * HWW * DD];  // des2 NHWC

// ---------------------------------------------------------------------------
// Cell argmax sampling (first-max). Reference swaps x/y on unpack.
// ---------------------------------------------------------------------------
__global__ void sample_kernel(const float* __restrict__ det1,
                              const float* __restrict__ det2) {
    int t = blockIdx.x * blockDim.x + threadIdx.x;
    if (t >= 2 * NN) return;
    const float* det = (t < NN) ? det1 : det2;
    int s = (t < NN) ? t : (t - NN);
    int b = s / NPB;
    int r = s - b * NPB;
    int cy = r / HCC;
    int cx = r - cy * HCC;
    const float* base = det + (long long)b * HWW + (TT + cy * 8) * WW + (TT + cx * 8);
    float best = -__int_as_float(0x7f800000);
    int bi = 0, bj = 0;
    #pragma unroll
    for (int ii = 0; ii < 8; ii++) {
        #pragma unroll
        for (int jj = 0; jj < 8; jj++) {
            float v = base[ii * WW + jj];
            if (v > best) { best = v; bi = ii; bj = jj; }
        }
    }
    int y = TT + cx * 8 + bj;   // reference swap
    int x = TT + cy * 8 + bi;
    if (t < NN) { g_y1[s] = y; g_x1[s] = x; }
    else        { g_yd[s] = y; g_xd[s] = x; }
}

// ---------------------------------------------------------------------------
// Transpose des2 (B,C,H,W) -> NHWC. __ldcs: single-use streaming reads.
// ---------------------------------------------------------------------------
__global__ void __launch_bounds__(256) transpose_kernel(const float* __restrict__ des2) {
    __shared__ float t[128][33];
    int b = blockIdx.y;
    int p0 = blockIdx.x * 32;
    int w = threadIdx.x >> 5, l = threadIdx.x & 31;
    const float* src = des2 + (long long)b * DD * HWW + p0;
    #pragma unroll
    for (int i = 0; i < 16; i++) {
        int cch = w + 8 * i;
        t[cch][l] = __ldcs(&src[(long long)cch * HWW + l]);
    }
    __syncthreads();
    float* dst = g_des2t + ((long long)b * HWW + p0) * DD;
    #pragma unroll
    for (int j = 0; j < 4; j++) {
        int p = w + 8 * j;
        #pragma unroll
        for (int u = 0; u < 4; u++) {
            dst[p * DD + u * 32 + l] = t[u * 32 + l][p];
        }
    }
}

// ---------------------------------------------------------------------------
// Per-sample: s_des1 gather (k-permuted), distractor gather (fused), xy2+mask,
// pos(argmax)/neg scores, qlt, labels col 0. 4-way ILP over offsets.
// ---------------------------------------------------------------------------
__global__ void score_kernel(const float* __restrict__ des1,
                             const float* __restrict__ qlt1,
                             const float* __restrict__ qlt2,
                             const float* __restrict__ aflow,
                             float* __restrict__ out) {
    int s = blockIdx.x;
    int c = threadIdx.x;
    int b = s / NPB;
    __shared__ float sdes[128];
    __shared__ float spall[32];
    __shared__ int sxy[2];

    int y1 = g_y1[s], x1 = g_x1[s];
    float v = des1[((b * DD + c) * HH + y1) * WW + x1];
    sdes[c] = v;
    int pc = kperm(c);
    g_A[s * DD + pc] = to_tf32(v);

    // fused distractor gather (k-permuted)
    {
        long long pixd = (long long)b * HWW + g_yd[s] * WW + g_xd[s];
        g_B[s * DD + pc] = to_tf32(g_des2t[pixd * DD + c]);
    }

    if (c == 0) {
        float ax = aflow[((b * 2 + 0) * HH + y1) * WW + x1];
        float ay = aflow[((b * 2 + 1) * HH + y1) * WW + x1];
        int xi = (int)(ax + 0.5f);
        int yi = (int)(ay + 0.5f);
        sxy[0] = xi; sxy[1] = yi;
        g_x2[s] = xi; g_y2[s] = yi;
        out[MASK_OFF + s] = (xi >= 0 && yi >= 0 && xi < WW && yi < HH) ? 1.0f : 0.0f;
        out[LABELS_OFF + (long long)s * COLSZ] = 1.0f;   // rest zeroed by memset
    }
    __syncthreads();

    int x2 = sxy[0], y2 = sxy[1];
    int w = c >> 5, l = c & 31;
    float4 a = *(const float4*)&sdes[l * 4];
    const float* dt = g_des2t + (long long)b * HWW * DD;

    // pos offsets: warp w handles p = w + 4u; 4-way ILP batches
    for (int base = w; base < PP; base += 16) {
        int pi[4];
        float sum[4];
        float4 dv[4];
        #pragma unroll
        for (int u = 0; u < 4; u++) {
            int p = base + 4 * u;
            pi[u] = (p < PP) ? p : base;
        }
        #pragma unroll
        for (int u = 0; u < 4; u++) {
            int xx = min(max(x2 + c_pos[pi[u]].x, 0), WW - 1);
            int yy = min(max(y2 + c_pos[pi[u]].y, 0), HH - 1);
            dv[u] = *(const float4*)(dt + (yy * WW + xx) * DD + l * 4);
        }
        #pragma unroll
        for (int u = 0; u < 4; u++)
            sum[u] = a.x * dv[u].x + a.y * dv[u].y + a.z * dv[u].z + a.w * dv[u].w;
        #pragma unroll
        for (int o = 16; o > 0; o >>= 1) {
            #pragma unroll
            for (int u = 0; u < 4; u++)
                sum[u] += __shfl_down_sync(0xffffffffu, sum[u], o);
        }
        if (l == 0) {
            #pragma unroll
            for (int u = 0; u < 4; u++) {
                int p = base + 4 * u;
                if (p < PP) spall[p] = sum[u];
            }
        }
    }
    // neg offsets
    {
        int qi[4];
        float sum[4];
        float4 dv[4];
        #pragma unroll
        for (int u = 0; u < 4; u++) {
            int q = w + 4 * u;
            qi[u] = (q < QQ) ? q : w;
        }
        #pragma unroll
        for (int u = 0; u < 4; u++) {
            int xx = min(max(x2 + c_neg[qi[u]].x, 0), WW - 1);
            int yy = min(max(y2 + c_neg[qi[u]].y, 0), HH - 1);
            dv[u] = *(const float4*)(dt + (yy * WW + xx) * DD + l * 4);
        }
        #pragma unroll
        for (int u = 0; u < 4; u++)
            sum[u] = a.x * dv[u].x + a.y * dv[u].y + a.z * dv[u].z + a.w * dv[u].w;
        #pragma unroll
        for (int o = 16; o > 0; o >>= 1) {
            #pragma unroll
            for (int u = 0; u < 4; u++)
                sum[u] += __shfl_down_sync(0xffffffffu, sum[u], o);
        }
        if (l == 0) {
            #pragma unroll
            for (int u = 0; u < 4; u++) {
                int q = w + 4 * u;
                if (q < QQ) out[(long long)s * COLSZ + 1 + q] = sum[u];
            }
        }
    }
    __syncthreads();

    if (c == 0) {
        float best = spall[0]; int bp = 0;
        #pragma unroll
        for (int p = 1; p < PP; p++) {
            if (spall[p] > best) { best = spall[p]; bp = p; }
        }
        out[(long long)s * COLSZ] = best;
        int selx = min(max(x2 + c_pos[bp].x, 0), WW - 1);
        int sely = min(max(y2 + c_pos[bp].y, 0), HH - 1);
        float q1 = qlt1[(long long)b * HWW + y1 * WW + x1];
        float q2 = qlt2[(long long)b * HWW + sely * WW + selx];
        out[QLT_OFF + s] = 0.5f * (q1 + q2);
    }
}

// ---------------------------------------------------------------------------
// dscores GEMM via mma.sync tf32 (m16n8k8). CTA tile 128x128, 256 threads,
// 8 warps 2x4, warp tile 64x32 (R9 shape). k-permuted layout -> all fragment
// loads are LDS.64 (12 LDS per 16 MMA). Smem row stride 40 floats:
// conflict-free half-warp float2 pattern. 2-stage cp.async, 2 CTAs/SM.
// Grid exactly 49x49. Epilogue: dis2 mask + streaming stores.
// ---------------------------------------------------------------------------
#define GSTRIDE 40
#define GSTAGE_B (256 * GSTRIDE * 4)   // 40960 B (A rows 0-127, B rows 128-255)
#define GSMEM_B  (2 * GSTAGE_B)        // 81920 B

__global__ void __launch_bounds__(256, 2) gemm_kernel(float* __restrict__ out) {
    extern __shared__ char sm[];
    __shared__ int sqx[128], sqy[128], sqb[128];

    int tid = threadIdx.x;
    int wid = tid >> 5, lane = tid & 31;
    int gid = lane >> 2, t4 = lane & 3;
    int wr = wid >> 2, wc = wid & 3;     // 2x4 warp grid, warp tile 64x32
    int m0 = blockIdx.y * 128, n0 = blockIdx.x * 128;

    if (tid < 128) {
        int q = n0 + tid;
        sqx[tid] = g_xd[q]; sqy[tid] = g_yd[q]; sqb[tid] = q / NPB;
    }

    uint32_t sb = smem_u32(sm);
    int ldrow = tid >> 3, ldc4 = tid & 7;   // 32 rows per pass, 4 passes

    auto issue = [&](int st, int kc) {
        uint32_t so = sb + st * GSTAGE_B;
        #pragma unroll
        for (int i = 0; i < 4; i++) {
            int row = ldrow + 32 * i;
            cp16(so + row * (GSTRIDE * 4) + ldc4 * 16,
                 &g_A[(m0 + row) * DD + kc * 32 + ldc4 * 4]);
            cp16(so + (128 + row) * (GSTRIDE * 4) + ldc4 * 16,
                 &g_B[(n0 + row) * DD + kc * 32 + ldc4 * 4]);
        }
        CP_COMMIT();
    };

    issue(0, 0);
    issue(1, 1);

    float acc[4][4][4];
    #pragma unroll
    for (int i = 0; i < 4; i++)
        #pragma unroll
        for (int j = 0; j < 4; j++)
            #pragma unroll
            for (int cc = 0; cc < 4; cc++) acc[i][j][cc] = 0.0f;

    #pragma unroll
    for (int kc = 0; kc < 4; kc++) {
        if (kc < 3) { CP_WAIT(1); } else { CP_WAIT(0); }
        __syncthreads();

        const float* As = (const float*)(sm + (kc & 1) * GSTAGE_B);
        const float* Bsp = As + 128 * GSTRIDE;

        #pragma unroll
        for (int kk = 0; kk < 4; kk++) {
            int kb = kk * 8;
            uint32_t af[4][4], bf[4][2];
            #pragma unroll
            for (int i = 0; i < 4; i++) {
                int r = wr * 64 + i * 16 + gid;
                float2 lo = *(const float2*)&As[r * GSTRIDE + kb + 2 * t4];
                float2 hi = *(const float2*)&As[(r + 8) * GSTRIDE + kb + 2 * t4];
                af[i][0] = __float_as_uint(lo.x);
                af[i][1] = __float_as_uint(hi.x);
                af[i][2] = __float_as_uint(lo.y);
                af[i][3] = __float_as_uint(hi.y);
            }
            #pragma unroll
            for (int j = 0; j < 4; j++) {
                int nr = wc * 32 + j * 8 + gid;
                float2 bv = *(const float2*)&Bsp[nr * GSTRIDE + kb + 2 * t4];
                bf[j][0] = __float_as_uint(bv.x);
                bf[j][1] = __float_as_uint(bv.y);
            }
            #pragma unroll
            for (int i = 0; i < 4; i++)
                #pragma unroll
                for (int j = 0; j < 4; j++)
                    mma_tf32(acc[i][j], af[i], bf[j]);
        }

        if (kc + 2 < 4) {
            __syncthreads();          // stage kc&1 fully consumed
            issue(kc & 1, kc + 2);
        }
    }

    // Epilogue: scores with dis2 mask (streaming stores). Labels pre-zeroed.
    #pragma unroll
    for (int i = 0; i < 4; i++) {
        int r0 = m0 + wr * 64 + i * 16 + gid;
        int r1 = r0 + 8;
        int rx0 = g_x2[r0], ry0 = g_y2[r0], rb0 = r0 / NPB;
        int rx1 = g_x2[r1], ry1 = g_y2[r1], rb1 = r1 / NPB;
        long long s0 = (long long)r0 * COLSZ + 13 + n0;
        long long s1 = (long long)r1 * COLSZ + 13 + n0;
        #pragma unroll
        for (int j = 0; j < 4; j++) {
            int c0 = wc * 32 + j * 8 + t4 * 2;
            int c1 = c0 + 1;
            int dx, dy, d2;
            dx = sqx[c0] - rx0; dy = sqy[c0] - ry0;
            d2 = dx * dx + dy * dy + ((sqb[c0] != rb0) ? 9 : 0);
            __stcs(&out[s0 + c0], (d2 < 9) ? 0.0f : acc[i][j][0]);
            dx = sqx[c1] - rx0; dy = sqy[c1] - ry0;
            d2 = dx * dx + dy * dy + ((sqb[c1] != rb0) ? 9 : 0);
            __stcs(&out[s0 + c1], (d2 < 9) ? 0.0f : acc[i][j][1]);
            dx = sqx[c0] - rx1; dy = sqy[c0] - ry1;
            d2 = dx * dx + dy * dy + ((sqb[c0] != rb1) ? 9 : 0);
            __stcs(&out[s1 + c0], (d2 < 9) ? 0.0f : acc[i][j][2]);
            dx = sqx[c1] - rx1; dy = sqy[c1] - ry1;
            d2 = dx * dx + dy * dy + ((sqb[c1] != rb1) ? 9 : 0);
            __stcs(&out[s1 + c1], (d2 < 9) ? 0.0f : acc[i][j][3]);
        }
    }
}

extern "C" void kernel_launch(void* const* d_in, const int* in_sizes, int n_in,
                              void* d_out, int out_size) {
    const float* des1  = (const float*)d_in[0];
    const float* det1  = (const float*)d_in[1];
    const float* qlt1  = (const float*)d_in[2];
    const float* des2  = (const float*)d_in[3];
    const float* det2  = (const float*)d_in[4];
    const float* qlt2  = (const float*)d_in[5];
    const float* aflow = (const float*)d_in[6];
    float* out = (float*)d_out;

    cudaFuncSetAttribute(gemm_kernel, cudaFuncAttributeMaxDynamicSharedMemorySize, GSMEM_B);

    // Zero the labels plane up front (graph memset node); score sets col 0 = 1.
    cudaMemsetAsync(out + LABELS_OFF, 0, (size_t)NN * COLSZ * sizeof(float));

    sample_kernel<<<(2 * NN + 255) / 256, 256>>>(det1, det2);
    transpose_kernel<<<dim3(HWW / 32, BB), 256>>>(des2);
    score_kernel<<<NN, 128>>>(des1, qlt1, qlt2, aflow, out);
    gemm_kernel<<<dim3(49, 49), 256, GSMEM_B>>>(out);
}